// round 11
// baseline (speedup 1.0000x reference)
#include <cuda_runtime.h>
#include <cstdint>

// EmbeddingBagCollection: T=8 tables [V=100000, D=128] fp32, indices [T,B=4096,L=50] int32.
// out[b, t*D + d] = sum_{l} tables[t, indices[t,b,l], d]
//
// Persistent grid: 592 CTAs (148 SM x 4 resident), each warp handles 7 bags
// (bag = it*4736 + gwarp) -> zero wave transitions, table-major locality kept
// (each iteration's active bag set spans ~1.16 tables -> full L2 dedup).
// Indices: 2 coalesced LDGs into registers, distributed via __shfl_sync
// (no smem, no __syncthreads -> warps free-run).
// Rows: batched 10-deep ld.global.cg.v4 gathers. Output: streaming store.

#define T_TABLES 8
#define B_BATCH  4096
#define L_BAG    50
#define V_VOCAB  100000
#define D_DIM    128
#define CHUNK    10
#define NUM_CTAS 592
#define WARPS_PER_BLOCK 8
#define TOTAL_BAGS (T_TABLES * B_BATCH)             // 32768
#define WARP_SLOTS (NUM_CTAS * WARPS_PER_BLOCK)     // 4736
#define NUM_ITERS  ((TOTAL_BAGS + WARP_SLOTS - 1) / WARP_SLOTS)  // 7

__device__ __forceinline__ float4 ldg_cg_f4(const float* p) {
    float4 v;
    asm volatile("ld.global.cg.v4.f32 {%0,%1,%2,%3}, [%4];"
                 : "=f"(v.x), "=f"(v.y), "=f"(v.z), "=f"(v.w)
                 : "l"(p));
    return v;
}

__device__ __forceinline__ void stg_cs_f4(float* p, float4 v) {
    asm volatile("st.global.cs.v4.f32 [%0], {%1,%2,%3,%4};"
                 :: "l"(p), "f"(v.x), "f"(v.y), "f"(v.z), "f"(v.w)
                 : "memory");
}

__global__ void __launch_bounds__(256, 4)
ebc_kernel(const int*   __restrict__ indices,
           const float* __restrict__ tables,
           float*       __restrict__ out)
{
    const int lane  = threadIdx.x & 31;
    const int gwarp = blockIdx.x * WARPS_PER_BLOCK + (threadIdx.x >> 5);

    #pragma unroll 1
    for (int it = 0; it < NUM_ITERS; ++it) {
        const int bag_id = it * WARP_SLOTS + gwarp;
        if (bag_id >= TOTAL_BAGS) return;   // only last iteration can exit

        const int t = bag_id / B_BATCH;     // table id (table-major)
        const int b = bag_id % B_BATCH;     // bag id

        // Load this warp's 50 indices into 2 regs/lane (coalesced), shfl later.
        const int* __restrict__ bag = indices + (size_t)bag_id * L_BAG;
        const int i0 = bag[lane];                           // idx[0..31]
        const int i1 = (lane < L_BAG - 32) ? bag[32 + lane] : 0;  // idx[32..49]

        const float* __restrict__ tab = tables + (size_t)t * V_VOCAB * D_DIM
                                               + (size_t)lane * 4;

        float4 acc = make_float4(0.f, 0.f, 0.f, 0.f);

        #pragma unroll
        for (int base = 0; base < L_BAG; base += CHUNK) {
            float4 v[CHUNK];
            #pragma unroll
            for (int j = 0; j < CHUNK; ++j) {
                const int jj = base + j;                    // compile-time
                const int r  = (jj < 32)
                             ? __shfl_sync(0xffffffffu, i0, jj)
                             : __shfl_sync(0xffffffffu, i1, jj - 32);
                v[j] = ldg_cg_f4(tab + (size_t)r * D_DIM);
            }
            #pragma unroll
            for (int j = 0; j < CHUNK; ++j) {
                acc.x += v[j].x;
                acc.y += v[j].y;
                acc.z += v[j].z;
                acc.w += v[j].w;
            }
        }

        stg_cs_f4(out + (size_t)b * (T_TABLES * D_DIM) + t * D_DIM + lane * 4, acc);
    }
}

extern "C" void kernel_launch(void* const* d_in, const int* in_sizes, int n_in,
                              void* d_out, int out_size)
{
    const long long N_IDX = (long long)T_TABLES * B_BATCH * L_BAG;

    const int*   indices;
    const float* tables;
    if ((long long)in_sizes[0] == N_IDX) {
        indices = (const int*)d_in[0];
        tables  = (const float*)d_in[1];
    } else {
        indices = (const int*)d_in[1];
        tables  = (const float*)d_in[0];
    }
    float* out = (float*)d_out;

    ebc_kernel<<<NUM_CTAS, 256>>>(indices, tables, out);
}